// round 13
// baseline (speedup 1.0000x reference)
#include <cuda_runtime.h>
#include <cuda_fp16.h>
#include <mma.h>
#include <cstdint>

using namespace nvcuda;

#define MAX_NODES 100000
#define HID   128
#define KEXT  144         // 128 Z dims + 1 bias row + 15 zero pad
#define LDA2  152         // sA row stride (halves): 304B/row, 16B-aligned, conflict-free
#define LDB2  264         // sB row stride (halves): 256 + 8 pad
#define MTILE 32          // GEMM m-tile rows (100000 % 32 == 0 -> all tiles full)
#define PGRID 296         // persistent CTAs = 148 SMs * 2

// Per-node projections, fp16 (51.2 MB total -> L2-resident).
// g_U = Z @ W1[0:128,:] + b1 (bias folded via K-extension row); g_V = Z @ W1[128:256,:].
__device__ __half g_U[(size_t)MAX_NODES * HID];
__device__ __half g_V[(size_t)MAX_NODES * HID];
__device__ __half g_Zh[(size_t)MAX_NODES * HID];   // Z pre-converted to fp16

extern __shared__ char smem_raw[];

// ---- cp.async helpers ------------------------------------------------------
__device__ __forceinline__ void cp16(uint32_t dst_smem, const void* src) {
    asm volatile("cp.async.cg.shared.global [%0], [%1], 16;" :: "r"(dst_smem), "l"(src));
}
__device__ __forceinline__ void cp_commit() {
    asm volatile("cp.async.commit_group;");
}
template <int N> __device__ __forceinline__ void cp_wait() {
    asm volatile("cp.async.wait_group %0;" :: "n"(N));
}

// ---------------------------------------------------------------------------
// Z fp32 -> fp16 streaming convert (one-shot; makes GEMM A-staging trivial).
// ---------------------------------------------------------------------------
__global__ void __launch_bounds__(256)
zh_convert(const float* __restrict__ z, int n_elems)
{
    int i = (blockIdx.x * 256 + threadIdx.x) * 8;
    if (i < n_elems) {
        float4 a = *(const float4*)(z + i);
        float4 b = *(const float4*)(z + i + 4);
        __half2 h[4];
        h[0] = __floats2half2_rn(a.x, a.y);
        h[1] = __floats2half2_rn(a.z, a.w);
        h[2] = __floats2half2_rn(b.x, b.y);
        h[3] = __floats2half2_rn(b.z, b.w);
        *(uint4*)(g_Zh + i) = *(uint4*)h;
    }
}

// ---------------------------------------------------------------------------
// Persistent fused precompute with cp.async double-buffered A.
// 296 CTAs; each stages combined B (144x256 fp16: U wts | V wts, bias row)
// once, then strides over 32-row m-tiles. A tiles stream from g_Zh via
// cp.async into 2 buffers; MMA(t) overlaps the copy of tile t+1.
// 8 warps = 2 m x 4 n, warp tile 16x64. Epilogue: f32 acc -> f16 fragment ->
// store_matrix_sync direct to g_U / g_V.
// smem = 2*32*152*2 + 144*264*2 = 95,488 B -> 2 CTAs/SM.
// ---------------------------------------------------------------------------
__global__ void __launch_bounds__(256)
lp_precompute(const float* __restrict__ W1,
              const float* __restrict__ b1,
              int n_nodes)
{
    __half* sA0 = (__half*)smem_raw;                 // [32][LDA2]
    __half* sA1 = sA0 + MTILE * LDA2;                // [32][LDA2]
    __half* sB  = sA1 + MTILE * LDA2;                // [KEXT][LDB2]
    __half* sAbuf[2] = { sA0, sA1 };

    const int tid    = threadIdx.x;
    const int ntiles = (n_nodes + MTILE - 1) / MTILE;

    // ---- one-time B stage: combined [k][n]; n<128 -> W1[k][n], n>=128 -> W1[128+k][n-128]
    for (int idx = tid; idx < 128 * 64; idx += 256) {
        const int r  = idx >> 6;
        const int c4 = (idx & 63) << 2;
        const float* src = (c4 < 128)
            ? (W1 + (size_t)r * HID + c4)
            : (W1 + (size_t)(128 + r) * HID + (c4 - 128));
        const float4 f = *(const float4*)src;
        __half2 h[2];
        h[0] = __floats2half2_rn(f.x, f.y);
        h[1] = __floats2half2_rn(f.z, f.w);
        *(uint2*)(sB + r * LDB2 + c4) = *(uint2*)h;
    }
    // B rows 128..143: row 128 = [b1 | 0], remainder zero
    for (int idx = tid; idx < 16 * 64; idx += 256) {
        const int r  = 128 + (idx >> 6);
        const int c4 = (idx & 63) << 2;
        __half2 h[2];
        if (r == 128 && c4 < 128) {
            const float4 f = *(const float4*)(b1 + c4);
            h[0] = __floats2half2_rn(f.x, f.y);
            h[1] = __floats2half2_rn(f.z, f.w);
        } else {
            h[0] = h[1] = __floats2half2_rn(0.f, 0.f);
        }
        *(uint2*)(sB + r * LDB2 + c4) = *(uint2*)h;
    }
    // A constant cols 128..143 in BOTH buffers (col 128 = 1.0 bias mult, rest 0).
    // cp.async only ever writes cols 0..127, so these survive all tiles.
    for (int i = tid; i < MTILE * 4 * 2; i += 256) {
        const int buf = i >= MTILE * 4;
        const int j   = i - buf * MTILE * 4;
        const int r   = j >> 2;
        const int c4  = 128 + (j & 3) * 4;
        __half h4[4];
        h4[0] = __float2half((c4 == 128) ? 1.0f : 0.0f);
        h4[1] = __float2half(0.0f);
        h4[2] = __float2half(0.0f);
        h4[3] = __float2half(0.0f);
        *(uint2*)(sAbuf[buf] + r * LDA2 + c4) = *(uint2*)h4;
    }

    // smem u32 addresses for cp.async
    uint32_t aAddr[2];
    aAddr[0] = (uint32_t)__cvta_generic_to_shared(sA0);
    aAddr[1] = (uint32_t)__cvta_generic_to_shared(sA1);

    // stage-issue lambda: 512 x 16B chunks per tile -> 2 cp.async per thread
    auto stage_issue = [&](int tile, int buf) {
        const int m0 = tile * MTILE;
        #pragma unroll
        for (int i = 0; i < 2; i++) {
            const int idx = tid + i * 256;       // 0..511
            const int r   = idx >> 4;            // row 0..31
            const int c8  = (idx & 15) << 3;     // half-col 0,8,..,120
            const int row = min(m0 + r, n_nodes - 1);   // clamp (never stored if invalid)
            cp16(aAddr[buf] + (uint32_t)(r * LDA2 + c8) * 2,
                 g_Zh + (size_t)row * HID + c8);
        }
    };

    const int warpId = tid >> 5;
    const int wm = (warpId & 1) * 16;            // warp m offset (0/16)
    const int wn = (warpId >> 1) * 64;           // warp n offset (0/64/128/192)
    __half* const outb = (wn < 128) ? g_U : g_V;
    const int ocol = (wn < 128) ? wn : wn - 128;

    int tile = blockIdx.x;
    if (tile < ntiles) stage_issue(tile, 0);
    cp_commit();                                  // empty group ok if no work

    int cur = 0;
    for (; tile < ntiles; tile += PGRID) {
        const int  nxt      = tile + PGRID;
        const bool havenext = (nxt < ntiles);

        if (havenext) {
            stage_issue(nxt, cur ^ 1);
            cp_commit();
            cp_wait<1>();                         // tile 'cur' data arrived
        } else {
            cp_wait<0>();
        }
        __syncthreads();                          // A(cur), B, const cols visible

        const int m0 = tile * MTILE;
        if (m0 + wm < n_nodes) {                  // n_nodes % 16 == 0
            __half* const sA = sAbuf[cur];
            wmma::fragment<wmma::accumulator, 16, 16, 16, float> acc[4];
            #pragma unroll
            for (int j = 0; j < 4; j++) wmma::fill_fragment(acc[j], 0.0f);

            #pragma unroll
            for (int k0 = 0; k0 < KEXT; k0 += 16) {
                wmma::fragment<wmma::matrix_a, 16, 16, 16, __half, wmma::row_major> a;
                wmma::load_matrix_sync(a, sA + wm * LDA2 + k0, LDA2);
                #pragma unroll
                for (int j = 0; j < 4; j++) {
                    wmma::fragment<wmma::matrix_b, 16, 16, 16, __half, wmma::row_major> b;
                    wmma::load_matrix_sync(b, sB + k0 * LDB2 + wn + j * 16, LDB2);
                    wmma::mma_sync(acc[j], a, b, acc[j]);
                }
            }

            #pragma unroll
            for (int j = 0; j < 4; j++) {
                wmma::fragment<wmma::accumulator, 16, 16, 16, __half> hacc;
                #pragma unroll
                for (int i = 0; i < hacc.num_elements; i++)
                    hacc.x[i] = __float2half(acc[j].x[i]);
                wmma::store_matrix_sync(outb + (size_t)(m0 + wm) * HID + ocol + j * 16,
                                        hacc, HID, wmma::mem_row_major);
            }
        }
        __syncthreads();                          // all reads of A(cur) done before refill
        cur ^= 1;
    }
}

// ---------------------------------------------------------------------------
// Edge kernel: 16 lanes per edge-slot, 2 slots per warp, 2 edges per slot per
// iteration. relu(u+v) fused into ONE fma.rn.relu.f16x2 (u*1+v, clamped at 0),
// then hfma2 dot; fp32 shfl-pair reduce; sigmoid.
// ---------------------------------------------------------------------------
__device__ __forceinline__ __half2 hfma2_relu(__half2 a, __half2 b, __half2 c) {
    uint32_t r;
    asm("fma.rn.relu.f16x2 %0, %1, %2, %3;"
        : "=r"(r)
        : "r"(*(const uint32_t*)&a), "r"(*(const uint32_t*)&b),
          "r"(*(const uint32_t*)&c));
    return *(__half2*)&r;
}

__global__ void __launch_bounds__(256)
lp_edge(const int* __restrict__ ei,
        const float* __restrict__ W2,
        const float* __restrict__ b2,
        float* __restrict__ out,
        int E)
{
    const int lane = threadIdx.x & 31;
    const int sub  = lane >> 4;
    const int l16  = lane & 15;
    const int gw   = (blockIdx.x * blockDim.x + threadIdx.x) >> 5;
    const int nw   = (gridDim.x * blockDim.x) >> 5;

    __half2 w2h[4];
    {
        const float* w2p = W2 + l16 * 8;
        #pragma unroll
        for (int j = 0; j < 4; j++)
            w2h[j] = __floats2half2_rn(w2p[2 * j], w2p[2 * j + 1]);
    }
    const float   b2v   = __ldg(b2);
    const __half2 zero2 = __floats2half2_rn(0.f, 0.f);
    const __half2 one2  = __floats2half2_rn(1.f, 1.f);

    const __half* Ub = g_U + l16 * 8;
    const __half* Vb = g_V + l16 * 8;

    for (int e4 = gw * 4; e4 < E; e4 += nw * 4) {
        const int  eA = e4 + sub * 2;
        const int  eB = eA + 1;
        const bool vA = (eA < E);
        const bool vB = (eB < E);

        const int s0 = vA ? __ldg(ei + eA)     : 0;
        const int d0 = vA ? __ldg(ei + E + eA) : 0;
        const int s1 = vB ? __ldg(ei + eB)     : 0;
        const int d1 = vB ? __ldg(ei + E + eB) : 0;

        const uint4 u0 = *(const uint4*)(Ub + (size_t)s0 * HID);
        const uint4 v0 = *(const uint4*)(Vb + (size_t)d0 * HID);
        const uint4 u1 = *(const uint4*)(Ub + (size_t)s1 * HID);
        const uint4 v1 = *(const uint4*)(Vb + (size_t)d1 * HID);

        const __half2* u0h = (const __half2*)&u0;
        const __half2* v0h = (const __half2*)&v0;
        const __half2* u1h = (const __half2*)&u1;
        const __half2* v1h = (const __half2*)&v1;

        __half2 p0 = zero2, p1 = zero2;
        #pragma unroll
        for (int j = 0; j < 4; j++) {
            const __half2 t0 = hfma2_relu(u0h[j], one2, v0h[j]);  // relu(u+v)
            const __half2 t1 = hfma2_relu(u1h[j], one2, v1h[j]);
            p0 = __hfma2(t0, w2h[j], p0);
            p1 = __hfma2(t1, w2h[j], p1);
        }

        float a0 = __low2float(p0) + __high2float(p0);
        float a1 = __low2float(p1) + __high2float(p1);

        #pragma unroll
        for (int o = 8; o; o >>= 1) {
            a0 += __shfl_xor_sync(0xffffffffu, a0, o);
            a1 += __shfl_xor_sync(0xffffffffu, a1, o);
        }

        if (l16 == 0) {
            if (vA) out[eA] = 1.0f / (1.0f + __expf(-(a0 + b2v)));
            if (vB) out[eB] = 1.0f / (1.0f + __expf(-(a1 + b2v)));
        }
    }
}

// ---------------------------------------------------------------------------
// inputs: z f32[100000*128], edge_index i32[2*1000000],
//         W1 f32[256*128], b1 f32[128], W2 f32[128], b2 f32[1]
// output: f32[1000000]
// ---------------------------------------------------------------------------
extern "C" void kernel_launch(void* const* d_in, const int* in_sizes, int n_in,
                              void* d_out, int out_size)
{
    (void)n_in; (void)out_size;
    const float* z  = (const float*)d_in[0];
    const int*   ei = (const int*)  d_in[1];
    const float* W1 = (const float*)d_in[2];
    const float* b1 = (const float*)d_in[3];
    const float* W2 = (const float*)d_in[4];
    const float* b2 = (const float*)d_in[5];

    const int n_elems = in_sizes[0];             // n_nodes * HID
    const int n_nodes = n_elems / HID;
    const int E       = in_sizes[1] / 2;

    zh_convert<<<(n_elems / 8 + 255) / 256, 256>>>(z, n_elems);

    const int smem_bytes = (2 * MTILE * LDA2 + KEXT * LDB2) * (int)sizeof(__half);  // 95,488 B
    cudaFuncSetAttribute(lp_precompute,
                         cudaFuncAttributeMaxDynamicSharedMemorySize, smem_bytes);
    lp_precompute<<<PGRID, 256, smem_bytes>>>(W1, b1, n_nodes);

    lp_edge<<<4440, 256>>>(ei, W2, b2, (float*)d_out, E);
}

// round 14
// speedup vs baseline: 1.1077x; 1.1077x over previous
#include <cuda_runtime.h>
#include <cuda_fp16.h>
#include <mma.h>
#include <cstdint>

using namespace nvcuda;

#define MAX_NODES 100000
#define HID   128
#define KEXT  144         // 128 Z dims + 1 bias row + 15 zero pad
#define LDA2  152         // sA row stride (halves): conflict-free ldmatrix
#define LDB2  264         // sB row stride (halves): 256 + 8 pad
#define NTILES 1563       // ceil(100000 / 64)
#define PGRID  296        // persistent CTAs = 148 SMs * 2

// Per-node projections, fp16 (51.2 MB total -> L2-resident).
// g_U = Z @ W1[0:128,:] + b1 (bias folded via K-extension row); g_V = Z @ W1[128:256,:].
__device__ __half g_U[(size_t)MAX_NODES * HID];
__device__ __half g_V[(size_t)MAX_NODES * HID];

extern __shared__ char smem_raw[];

// ---------------------------------------------------------------------------
// Persistent fused precompute (R11 design — measured 44.4us; the R8 register
// prefetch and R13 cp.async/pre-convert restructures both regressed it).
// 296 CTAs each stage the combined B (144x256 fp16: U half | V half, bias
// row) ONCE, then stride over 64-row m-tiles. Per tile: stage A (Z->fp16),
// 9 k-step HMMA into 64x256 (8 warps, 16x128 each), epilogue f32 acc -> f16
// fragment -> store_matrix_sync direct to g_U / g_V. Z DRAM-read once.
// ---------------------------------------------------------------------------
__global__ void __launch_bounds__(256)
lp_precompute(const float* __restrict__ z,
              const float* __restrict__ W1,
              const float* __restrict__ b1,
              int n_nodes)
{
    __half* sA = (__half*)smem_raw;              // [64][LDA2]
    __half* sB = sA + 64 * LDA2;                 // [KEXT][LDB2]

    const int tid = threadIdx.x;

    // One-time B stage: combined [k][n]; n<128 -> W1[k][n], n>=128 -> W1[128+k][n-128]
    for (int idx = tid; idx < 128 * 64; idx += 256) {
        const int r  = idx >> 6;
        const int c4 = (idx & 63) << 2;
        const float* src = (c4 < 128)
            ? (W1 + (size_t)r * HID + c4)
            : (W1 + (size_t)(128 + r) * HID + (c4 - 128));
        const float4 f = *(const float4*)src;
        __half2 h[2];
        h[0] = __floats2half2_rn(f.x, f.y);
        h[1] = __floats2half2_rn(f.z, f.w);
        *(uint2*)(sB + r * LDB2 + c4) = *(uint2*)h;
    }
    // B rows 128..143: row 128 = [b1 | 0], remainder zero
    for (int idx = tid; idx < 16 * 64; idx += 256) {
        const int r  = 128 + (idx >> 6);
        const int c4 = (idx & 63) << 2;
        __half2 h[2];
        if (r == 128 && c4 < 128) {
            const float4 f = *(const float4*)(b1 + c4);
            h[0] = __floats2half2_rn(f.x, f.y);
            h[1] = __floats2half2_rn(f.z, f.w);
        } else {
            h[0] = h[1] = __floats2half2_rn(0.f, 0.f);
        }
        *(uint2*)(sB + r * LDB2 + c4) = *(uint2*)h;
    }
    // A constant cols 128..143: col 128 = 1.0 (bias multiplier), rest 0; set once
    for (int i = tid; i < 64 * 4; i += 256) {
        const int r  = i >> 2;
        const int c4 = 128 + (i & 3) * 4;
        __half h4[4];
        h4[0] = __float2half((c4 == 128) ? 1.0f : 0.0f);
        h4[1] = __float2half(0.0f);
        h4[2] = __float2half(0.0f);
        h4[3] = __float2half(0.0f);
        *(uint2*)(sA + r * LDA2 + c4) = *(uint2*)h4;
    }

    const int warpId = tid >> 5;
    const int wm = (warpId & 3) * 16;            // warp m offset within tile
    const int nh = warpId >> 2;                  // 0 -> U half, 1 -> V half
    const int ncol = nh * 128;                   // sB column base for this warp
    __half* const outb = (nh == 0) ? g_U : g_V;

    #pragma unroll 1
    for (int tile = blockIdx.x; tile < NTILES; tile += PGRID) {
        const int m0   = tile * 64;
        const int mrem = n_nodes - m0;

        __syncthreads();   // prior MMA done reading sA (and sB ready on t=0)

        // Stage A cols 0..127: Z fp32 -> fp16, zero-pad past-end rows
        for (int idx = tid; idx < 64 * 32; idx += 256) {
            const int r  = idx >> 5;
            const int c4 = (idx & 31) << 2;
            __half2 h[2];
            if (r < mrem) {
                const float4 f = *(const float4*)(z + (size_t)(m0 + r) * HID + c4);
                h[0] = __floats2half2_rn(f.x, f.y);
                h[1] = __floats2half2_rn(f.z, f.w);
            } else {
                h[0] = h[1] = __floats2half2_rn(0.f, 0.f);
            }
            *(uint2*)(sA + r * LDA2 + c4) = *(uint2*)h;
        }
        __syncthreads();

        if (m0 + wm < n_nodes) {                 // n_nodes % 16 == 0
            wmma::fragment<wmma::accumulator, 16, 16, 16, float> acc[8];
            #pragma unroll
            for (int j = 0; j < 8; j++) wmma::fill_fragment(acc[j], 0.0f);

            #pragma unroll
            for (int k0 = 0; k0 < KEXT; k0 += 16) {
                wmma::fragment<wmma::matrix_a, 16, 16, 16, __half, wmma::row_major> a;
                wmma::load_matrix_sync(a, sA + wm * LDA2 + k0, LDA2);
                #pragma unroll
                for (int j = 0; j < 8; j++) {
                    wmma::fragment<wmma::matrix_b, 16, 16, 16, __half, wmma::row_major> b;
                    wmma::load_matrix_sync(b, sB + k0 * LDB2 + ncol + j * 16, LDB2);
                    wmma::mma_sync(acc[j], a, b, acc[j]);
                }
            }

            #pragma unroll
            for (int j = 0; j < 8; j++) {
                wmma::fragment<wmma::accumulator, 16, 16, 16, __half> hacc;
                #pragma unroll
                for (int i = 0; i < hacc.num_elements; i++)
                    hacc.x[i] = __float2half(acc[j].x[i]);
                wmma::store_matrix_sync(outb + (size_t)(m0 + wm) * HID + j * 16,
                                        hacc, HID, wmma::mem_row_major);
            }
        }
    }
}

// ---------------------------------------------------------------------------
// Edge kernel: 16 lanes per edge-slot, 2 slots per warp, 2 edges per slot per
// iteration. relu(u+v) fused into ONE fma.rn.relu.f16x2 (u*1+v clamped at 0),
// then hfma2 dot; fp32 shfl-pair reduce; sigmoid.
// ---------------------------------------------------------------------------
__device__ __forceinline__ __half2 hfma2_relu(__half2 a, __half2 b, __half2 c) {
    uint32_t r;
    asm("fma.rn.relu.f16x2 %0, %1, %2, %3;"
        : "=r"(r)
        : "r"(*(const uint32_t*)&a), "r"(*(const uint32_t*)&b),
          "r"(*(const uint32_t*)&c));
    return *(__half2*)&r;
}

__global__ void __launch_bounds__(256)
lp_edge(const int* __restrict__ ei,
        const float* __restrict__ W2,
        const float* __restrict__ b2,
        float* __restrict__ out,
        int E)
{
    const int lane = threadIdx.x & 31;
    const int sub  = lane >> 4;
    const int l16  = lane & 15;
    const int gw   = (blockIdx.x * blockDim.x + threadIdx.x) >> 5;
    const int nw   = (gridDim.x * blockDim.x) >> 5;

    __half2 w2h[4];
    {
        const float* w2p = W2 + l16 * 8;
        #pragma unroll
        for (int j = 0; j < 4; j++)
            w2h[j] = __floats2half2_rn(w2p[2 * j], w2p[2 * j + 1]);
    }
    const float   b2v   = __ldg(b2);
    const __half2 zero2 = __floats2half2_rn(0.f, 0.f);
    const __half2 one2  = __floats2half2_rn(1.f, 1.f);

    const __half* Ub = g_U + l16 * 8;
    const __half* Vb = g_V + l16 * 8;

    for (int e4 = gw * 4; e4 < E; e4 += nw * 4) {
        const int  eA = e4 + sub * 2;
        const int  eB = eA + 1;
        const bool vA = (eA < E);
        const bool vB = (eB < E);

        const int s0 = vA ? __ldg(ei + eA)     : 0;
        const int d0 = vA ? __ldg(ei + E + eA) : 0;
        const int s1 = vB ? __ldg(ei + eB)     : 0;
        const int d1 = vB ? __ldg(ei + E + eB) : 0;

        const uint4 u0 = *(const uint4*)(Ub + (size_t)s0 * HID);
        const uint4 v0 = *(const uint4*)(Vb + (size_t)d0 * HID);
        const uint4 u1 = *(const uint4*)(Ub + (size_t)s1 * HID);
        const uint4 v1 = *(const uint4*)(Vb + (size_t)d1 * HID);

        const __half2* u0h = (const __half2*)&u0;
        const __half2* v0h = (const __half2*)&v0;
        const __half2* u1h = (const __half2*)&u1;
        const __half2* v1h = (const __half2*)&v1;

        __half2 p0 = zero2, p1 = zero2;
        #pragma unroll
        for (int j = 0; j < 4; j++) {
            const __half2 t0 = hfma2_relu(u0h[j], one2, v0h[j]);  // relu(u+v)
            const __half2 t1 = hfma2_relu(u1h[j], one2, v1h[j]);
            p0 = __hfma2(t0, w2h[j], p0);
            p1 = __hfma2(t1, w2h[j], p1);
        }

        float a0 = __low2float(p0) + __high2float(p0);
        float a1 = __low2float(p1) + __high2float(p1);

        #pragma unroll
        for (int o = 8; o; o >>= 1) {
            a0 += __shfl_xor_sync(0xffffffffu, a0, o);
            a1 += __shfl_xor_sync(0xffffffffu, a1, o);
        }

        if (l16 == 0) {
            if (vA) out[eA] = 1.0f / (1.0f + __expf(-(a0 + b2v)));
            if (vB) out[eB] = 1.0f / (1.0f + __expf(-(a1 + b2v)));
        }
    }
}

// ---------------------------------------------------------------------------
// inputs: z f32[100000*128], edge_index i32[2*1000000],
//         W1 f32[256*128], b1 f32[128], W2 f32[128], b2 f32[1]
// output: f32[1000000]
// ---------------------------------------------------------------------------
extern "C" void kernel_launch(void* const* d_in, const int* in_sizes, int n_in,
                              void* d_out, int out_size)
{
    (void)n_in; (void)out_size;
    const float* z  = (const float*)d_in[0];
    const int*   ei = (const int*)  d_in[1];
    const float* W1 = (const float*)d_in[2];
    const float* b1 = (const float*)d_in[3];
    const float* W2 = (const float*)d_in[4];
    const float* b2 = (const float*)d_in[5];

    const int n_nodes = in_sizes[0] / HID;
    const int E       = in_sizes[1] / 2;

    const int smem_bytes = (64 * LDA2 + KEXT * LDB2) * (int)sizeof(__half);  // 95,488 B
    cudaFuncSetAttribute(lp_precompute,
                         cudaFuncAttributeMaxDynamicSharedMemorySize, smem_bytes);

    lp_precompute<<<PGRID, 256, smem_bytes>>>(z, W1, b1, n_nodes);

    lp_edge<<<4440, 256>>>(ei, W2, b2, (float*)d_out, E);
}

// round 15
// speedup vs baseline: 1.1569x; 1.0444x over previous
#include <cuda_runtime.h>
#include <cuda_fp16.h>
#include <mma.h>
#include <cstdint>

using namespace nvcuda;

#define MAX_NODES 100000
#define HID   128
#define KEXT  144         // 128 Z dims + 1 bias row + 15 zero pad
#define LDA2  152         // sA row stride (halves): conflict-free ldmatrix
#define LDB2  264         // sB row stride (halves): 256 + 8 pad
#define NTILES 1563       // ceil(100000 / 64)
#define PGRID  296        // persistent CTAs = 148 SMs * 2

// Per-node projections, fp16 (51.2 MB total -> L2-resident).
// g_U = Z @ W1[0:128,:] + b1 (bias folded via K-extension row); g_V = Z @ W1[128:256,:].
__device__ __half g_U[(size_t)MAX_NODES * HID];
__device__ __half g_V[(size_t)MAX_NODES * HID];

extern __shared__ char smem_raw[];

// ---------------------------------------------------------------------------
// Persistent fused precompute — FROZEN R11/R14 design (measured 44.2us; the
// R8 register-prefetch and R13 cp.async/pre-convert restructures regressed).
// 296 CTAs each stage the combined B (144x256 fp16: U half | V half, bias
// row) ONCE, then stride over 64-row m-tiles. Per tile: stage A (Z->fp16),
// 9 k-step HMMA into 64x256 (8 warps, 16x128 each), epilogue f32 acc -> f16
// fragment -> store_matrix_sync direct to g_U / g_V. Z DRAM-read once.
// ---------------------------------------------------------------------------
__global__ void __launch_bounds__(256)
lp_precompute(const float* __restrict__ z,
              const float* __restrict__ W1,
              const float* __restrict__ b1,
              int n_nodes)
{
    __half* sA = (__half*)smem_raw;              // [64][LDA2]
    __half* sB = sA + 64 * LDA2;                 // [KEXT][LDB2]

    const int tid = threadIdx.x;

    // One-time B stage: combined [k][n]; n<128 -> W1[k][n], n>=128 -> W1[128+k][n-128]
    for (int idx = tid; idx < 128 * 64; idx += 256) {
        const int r  = idx >> 6;
        const int c4 = (idx & 63) << 2;
        const float* src = (c4 < 128)
            ? (W1 + (size_t)r * HID + c4)
            : (W1 + (size_t)(128 + r) * HID + (c4 - 128));
        const float4 f = *(const float4*)src;
        __half2 h[2];
        h[0] = __floats2half2_rn(f.x, f.y);
        h[1] = __floats2half2_rn(f.z, f.w);
        *(uint2*)(sB + r * LDB2 + c4) = *(uint2*)h;
    }
    // B rows 128..143: row 128 = [b1 | 0], remainder zero
    for (int idx = tid; idx < 16 * 64; idx += 256) {
        const int r  = 128 + (idx >> 6);
        const int c4 = (idx & 63) << 2;
        __half2 h[2];
        if (r == 128 && c4 < 128) {
            const float4 f = *(const float4*)(b1 + c4);
            h[0] = __floats2half2_rn(f.x, f.y);
            h[1] = __floats2half2_rn(f.z, f.w);
        } else {
            h[0] = h[1] = __floats2half2_rn(0.f, 0.f);
        }
        *(uint2*)(sB + r * LDB2 + c4) = *(uint2*)h;
    }
    // A constant cols 128..143: col 128 = 1.0 (bias multiplier), rest 0; set once
    for (int i = tid; i < 64 * 4; i += 256) {
        const int r  = i >> 2;
        const int c4 = 128 + (i & 3) * 4;
        __half h4[4];
        h4[0] = __float2half((c4 == 128) ? 1.0f : 0.0f);
        h4[1] = __float2half(0.0f);
        h4[2] = __float2half(0.0f);
        h4[3] = __float2half(0.0f);
        *(uint2*)(sA + r * LDA2 + c4) = *(uint2*)h4;
    }

    const int warpId = tid >> 5;
    const int wm = (warpId & 3) * 16;            // warp m offset within tile
    const int nh = warpId >> 2;                  // 0 -> U half, 1 -> V half
    const int ncol = nh * 128;                   // sB column base for this warp
    __half* const outb = (nh == 0) ? g_U : g_V;

    #pragma unroll 1
    for (int tile = blockIdx.x; tile < NTILES; tile += PGRID) {
        const int m0   = tile * 64;
        const int mrem = n_nodes - m0;

        __syncthreads();   // prior MMA done reading sA (and sB ready on t=0)

        // Stage A cols 0..127: Z fp32 -> fp16, zero-pad past-end rows
        for (int idx = tid; idx < 64 * 32; idx += 256) {
            const int r  = idx >> 5;
            const int c4 = (idx & 31) << 2;
            __half2 h[2];
            if (r < mrem) {
                const float4 f = *(const float4*)(z + (size_t)(m0 + r) * HID + c4);
                h[0] = __floats2half2_rn(f.x, f.y);
                h[1] = __floats2half2_rn(f.z, f.w);
            } else {
                h[0] = h[1] = __floats2half2_rn(0.f, 0.f);
            }
            *(uint2*)(sA + r * LDA2 + c4) = *(uint2*)h;
        }
        __syncthreads();

        if (m0 + wm < n_nodes) {                 // n_nodes % 16 == 0
            wmma::fragment<wmma::accumulator, 16, 16, 16, float> acc[8];
            #pragma unroll
            for (int j = 0; j < 8; j++) wmma::fill_fragment(acc[j], 0.0f);

            #pragma unroll
            for (int k0 = 0; k0 < KEXT; k0 += 16) {
                wmma::fragment<wmma::matrix_a, 16, 16, 16, __half, wmma::row_major> a;
                wmma::load_matrix_sync(a, sA + wm * LDA2 + k0, LDA2);
                #pragma unroll
                for (int j = 0; j < 8; j++) {
                    wmma::fragment<wmma::matrix_b, 16, 16, 16, __half, wmma::row_major> b;
                    wmma::load_matrix_sync(b, sB + k0 * LDB2 + ncol + j * 16, LDB2);
                    wmma::mma_sync(acc[j], a, b, acc[j]);
                }
            }

            #pragma unroll
            for (int j = 0; j < 8; j++) {
                wmma::fragment<wmma::accumulator, 16, 16, 16, __half> hacc;
                #pragma unroll
                for (int i = 0; i < hacc.num_elements; i++)
                    hacc.x[i] = __float2half(acc[j].x[i]);
                wmma::store_matrix_sync(outb + (size_t)(m0 + wm) * HID + j * 16,
                                        hacc, HID, wmma::mem_row_major);
            }
        }
    }
}

// ---------------------------------------------------------------------------
// Edge kernel: 8 lanes per edge, 4 independent edges per warp. Lane l8 owns
// dims [8*l8, 8*l8+8) and [64+8*l8, 64+8*l8+8) — each of the 4 gather
// instructions covers a CONTIGUOUS 128B half-row per edge (dense wavefronts).
// relu(u+v) via fma.rn.relu.f16x2, two hfma2 dot accumulators (lo/hi) to
// break the dependency chain, 3-shfl reduce serving all 4 edges, sigmoid.
// ---------------------------------------------------------------------------
__device__ __forceinline__ __half2 hfma2_relu(__half2 a, __half2 b, __half2 c) {
    uint32_t r;
    asm("fma.rn.relu.f16x2 %0, %1, %2, %3;"
        : "=r"(r)
        : "r"(*(const uint32_t*)&a), "r"(*(const uint32_t*)&b),
          "r"(*(const uint32_t*)&c));
    return *(__half2*)&r;
}

__global__ void __launch_bounds__(256)
lp_edge(const int* __restrict__ ei,
        const float* __restrict__ W2,
        const float* __restrict__ b2,
        float* __restrict__ out,
        int E)
{
    const int lane = threadIdx.x & 31;
    const int sub  = lane >> 3;                  // edge slot 0..3
    const int l8   = lane & 7;                   // dim group
    const int gw   = (blockIdx.x * blockDim.x + threadIdx.x) >> 5;
    const int nw   = (gridDim.x * blockDim.x) >> 5;

    // W2 slices for this lane's dims: lo = [8*l8,+8), hi = [64+8*l8,+8)
    __half2 w2h[8];
    {
        const float* lo = W2 + l8 * 8;
        const float* hi = W2 + 64 + l8 * 8;
        #pragma unroll
        for (int j = 0; j < 4; j++) {
            w2h[j]     = __floats2half2_rn(lo[2 * j], lo[2 * j + 1]);
            w2h[4 + j] = __floats2half2_rn(hi[2 * j], hi[2 * j + 1]);
        }
    }
    const float   b2v   = __ldg(b2);
    const __half2 zero2 = __floats2half2_rn(0.f, 0.f);
    const __half2 one2  = __floats2half2_rn(1.f, 1.f);

    const __half* Ulo = g_U + l8 * 8;
    const __half* Uhi = g_U + 64 + l8 * 8;
    const __half* Vlo = g_V + l8 * 8;
    const __half* Vhi = g_V + 64 + l8 * 8;

    for (int e4 = gw * 4; e4 < E; e4 += nw * 4) {
        const int  e     = e4 + sub;
        const bool valid = (e < E);

        const int s = valid ? __ldg(ei + e)     : 0;
        const int d = valid ? __ldg(ei + E + e) : 0;

        const size_t so = (size_t)s * HID;
        const size_t dx = (size_t)d * HID;
        const uint4 ulo = *(const uint4*)(Ulo + so);
        const uint4 uhi = *(const uint4*)(Uhi + so);
        const uint4 vlo = *(const uint4*)(Vlo + dx);
        const uint4 vhi = *(const uint4*)(Vhi + dx);

        const __half2* ul = (const __half2*)&ulo;
        const __half2* uh = (const __half2*)&uhi;
        const __half2* vl = (const __half2*)&vlo;
        const __half2* vh = (const __half2*)&vhi;

        __half2 plo = zero2, phi = zero2;
        #pragma unroll
        for (int j = 0; j < 4; j++) {
            const __half2 tl = hfma2_relu(ul[j], one2, vl[j]);   // relu(u+v), lo dims
            const __half2 th = hfma2_relu(uh[j], one2, vh[j]);   // relu(u+v), hi dims
            plo = __hfma2(tl, w2h[j],     plo);
            phi = __hfma2(th, w2h[4 + j], phi);
        }

        const __half2 p = __hadd2(plo, phi);
        float a = __low2float(p) + __high2float(p);

        // 3-level reduce within each 8-lane group (all 4 edges in parallel)
        a += __shfl_xor_sync(0xffffffffu, a, 4);
        a += __shfl_xor_sync(0xffffffffu, a, 2);
        a += __shfl_xor_sync(0xffffffffu, a, 1);

        if (l8 == 0 && valid)
            out[e] = 1.0f / (1.0f + __expf(-(a + b2v)));
    }
}

// ---------------------------------------------------------------------------
// inputs: z f32[100000*128], edge_index i32[2*1000000],
//         W1 f32[256*128], b1 f32[128], W2 f32[128], b2 f32[1]
// output: f32[1000000]
// ---------------------------------------------------------------------------
extern "C" void kernel_launch(void* const* d_in, const int* in_sizes, int n_in,
                              void* d_out, int out_size)
{
    (void)n_in; (void)out_size;
    const float* z  = (const float*)d_in[0];
    const int*   ei = (const int*)  d_in[1];
    const float* W1 = (const float*)d_in[2];
    const float* b1 = (const float*)d_in[3];
    const float* W2 = (const float*)d_in[4];
    const float* b2 = (const float*)d_in[5];

    const int n_nodes = in_sizes[0] / HID;
    const int E       = in_sizes[1] / 2;

    const int smem_bytes = (64 * LDA2 + KEXT * LDB2) * (int)sizeof(__half);  // 95,488 B
    cudaFuncSetAttribute(lp_precompute,
                         cudaFuncAttributeMaxDynamicSharedMemorySize, smem_bytes);

    lp_precompute<<<PGRID, 256, smem_bytes>>>(z, W1, b1, n_nodes);

    lp_edge<<<4440, 256>>>(ei, W2, b2, (float*)d_out, E);
}

// round 16
// speedup vs baseline: 1.2391x; 1.0710x over previous
#include <cuda_runtime.h>
#include <cuda_fp16.h>
#include <mma.h>
#include <cstdint>

using namespace nvcuda;

#define MAX_NODES 100000
#define HID   128
#define KEXT  144         // 128 Z dims + 1 bias row + 15 zero pad
#define LDA2  152         // sA row stride (halves): conflict-free ldmatrix
#define LDB2  264         // sB row stride (halves): 256 + 8 pad
#define NTILES 1563       // ceil(100000 / 64)
#define PGRID  296        // persistent CTAs = 148 SMs * 2

// Per-node projections, fp16 (51.2 MB total).
// g_U = Z @ W1[0:128,:] + b1 (bias folded via K-extension row); g_V = Z @ W1[128:256,:].
__device__ __half g_U[(size_t)MAX_NODES * HID];
__device__ __half g_V[(size_t)MAX_NODES * HID];

extern __shared__ char smem_raw[];

// ---------------------------------------------------------------------------
// Persistent fused precompute — FROZEN R11/R14 design (measured ~45us; the
// R8 register-prefetch and R13 cp.async/pre-convert restructures regressed).
// ---------------------------------------------------------------------------
__global__ void __launch_bounds__(256)
lp_precompute(const float* __restrict__ z,
              const float* __restrict__ W1,
              const float* __restrict__ b1,
              int n_nodes)
{
    __half* sA = (__half*)smem_raw;              // [64][LDA2]
    __half* sB = sA + 64 * LDA2;                 // [KEXT][LDB2]

    const int tid = threadIdx.x;

    // One-time B stage: combined [k][n]; n<128 -> W1[k][n], n>=128 -> W1[128+k][n-128]
    for (int idx = tid; idx < 128 * 64; idx += 256) {
        const int r  = idx >> 6;
        const int c4 = (idx & 63) << 2;
        const float* src = (c4 < 128)
            ? (W1 + (size_t)r * HID + c4)
            : (W1 + (size_t)(128 + r) * HID + (c4 - 128));
        const float4 f = *(const float4*)src;
        __half2 h[2];
        h[0] = __floats2half2_rn(f.x, f.y);
        h[1] = __floats2half2_rn(f.z, f.w);
        *(uint2*)(sB + r * LDB2 + c4) = *(uint2*)h;
    }
    // B rows 128..143: row 128 = [b1 | 0], remainder zero
    for (int idx = tid; idx < 16 * 64; idx += 256) {
        const int r  = 128 + (idx >> 6);
        const int c4 = (idx & 63) << 2;
        __half2 h[2];
        if (r == 128 && c4 < 128) {
            const float4 f = *(const float4*)(b1 + c4);
            h[0] = __floats2half2_rn(f.x, f.y);
            h[1] = __floats2half2_rn(f.z, f.w);
        } else {
            h[0] = h[1] = __floats2half2_rn(0.f, 0.f);
        }
        *(uint2*)(sB + r * LDB2 + c4) = *(uint2*)h;
    }
    // A constant cols 128..143: col 128 = 1.0 (bias multiplier), rest 0; set once
    for (int i = tid; i < 64 * 4; i += 256) {
        const int r  = i >> 2;
        const int c4 = 128 + (i & 3) * 4;
        __half h4[4];
        h4[0] = __float2half((c4 == 128) ? 1.0f : 0.0f);
        h4[1] = __float2half(0.0f);
        h4[2] = __float2half(0.0f);
        h4[3] = __float2half(0.0f);
        *(uint2*)(sA + r * LDA2 + c4) = *(uint2*)h4;
    }

    const int warpId = tid >> 5;
    const int wm = (warpId & 3) * 16;            // warp m offset within tile
    const int nh = warpId >> 2;                  // 0 -> U half, 1 -> V half
    const int ncol = nh * 128;                   // sB column base for this warp
    __half* const outb = (nh == 0) ? g_U : g_V;

    #pragma unroll 1
    for (int tile = blockIdx.x; tile < NTILES; tile += PGRID) {
        const int m0   = tile * 64;
        const int mrem = n_nodes - m0;

        __syncthreads();   // prior MMA done reading sA (and sB ready on t=0)

        // Stage A cols 0..127: Z fp32 -> fp16, zero-pad past-end rows
        for (int idx = tid; idx < 64 * 32; idx += 256) {
            const int r  = idx >> 5;
            const int c4 = (idx & 31) << 2;
            __half2 h[2];
            if (r < mrem) {
                const float4 f = *(const float4*)(z + (size_t)(m0 + r) * HID + c4);
                h[0] = __floats2half2_rn(f.x, f.y);
                h[1] = __floats2half2_rn(f.z, f.w);
            } else {
                h[0] = h[1] = __floats2half2_rn(0.f, 0.f);
            }
            *(uint2*)(sA + r * LDA2 + c4) = *(uint2*)h;
        }
        __syncthreads();

        if (m0 + wm < n_nodes) {                 // n_nodes % 16 == 0
            wmma::fragment<wmma::accumulator, 16, 16, 16, float> acc[8];
            #pragma unroll
            for (int j = 0; j < 8; j++) wmma::fill_fragment(acc[j], 0.0f);

            #pragma unroll
            for (int k0 = 0; k0 < KEXT; k0 += 16) {
                wmma::fragment<wmma::matrix_a, 16, 16, 16, __half, wmma::row_major> a;
                wmma::load_matrix_sync(a, sA + wm * LDA2 + k0, LDA2);
                #pragma unroll
                for (int j = 0; j < 8; j++) {
                    wmma::fragment<wmma::matrix_b, 16, 16, 16, __half, wmma::row_major> b;
                    wmma::load_matrix_sync(b, sB + k0 * LDB2 + ncol + j * 16, LDB2);
                    wmma::mma_sync(acc[j], a, b, acc[j]);
                }
            }

            #pragma unroll
            for (int j = 0; j < 8; j++) {
                wmma::fragment<wmma::accumulator, 16, 16, 16, __half> hacc;
                #pragma unroll
                for (int i = 0; i < hacc.num_elements; i++)
                    hacc.x[i] = __float2half(acc[j].x[i]);
                wmma::store_matrix_sync(outb + (size_t)(m0 + wm) * HID + j * 16,
                                        hacc, HID, wmma::mem_row_major);
            }
        }
    }
}

// ---------------------------------------------------------------------------
// Edge kernel: 8 lanes per edge-slot, 4 slots per warp, 2 edges per slot per
// iteration (8 edges/warp/iter). All 8 gathers + 4 index loads issue before
// any math -> 2x memory-level parallelism per warp (latency-bound regime).
// Lane l8 owns dims [8*l8,+8) and [64+8*l8,+8): each gather instruction
// covers a contiguous 128B half-row per edge. relu(u+v) via fma.rn.relu.f16x2,
// dual hfma2 accumulators, 3-shfl reduce serving all 8 edges, sigmoid.
// ---------------------------------------------------------------------------
__device__ __forceinline__ __half2 hfma2_relu(__half2 a, __half2 b, __half2 c) {
    uint32_t r;
    asm("fma.rn.relu.f16x2 %0, %1, %2, %3;"
        : "=r"(r)
        : "r"(*(const uint32_t*)&a), "r"(*(const uint32_t*)&b),
          "r"(*(const uint32_t*)&c));
    return *(__half2*)&r;
}

__global__ void __launch_bounds__(256)
lp_edge(const int* __restrict__ ei,
        const float* __restrict__ W2,
        const float* __restrict__ b2,
        float* __restrict__ out,
        int E)
{
    const int lane = threadIdx.x & 31;
    const int sub  = lane >> 3;                  // edge slot 0..3
    const int l8   = lane & 7;                   // dim group
    const int gw   = (blockIdx.x * blockDim.x + threadIdx.x) >> 5;
    const int nw   = (gridDim.x * blockDim.x) >> 5;

    // W2 slices for this lane's dims: lo = [8*l8,+8), hi = [64+8*l8,+8)
    __half2 w2h[8];
    {
        const float* lo = W2 + l8 * 8;
        const float* hi = W2 + 64 + l8 * 8;
        #pragma unroll
        for (int j = 0; j < 4; j++) {
            w2h[j]     = __floats2half2_rn(lo[2 * j], lo[2 * j + 1]);
            w2h[4 + j] = __floats2half2_rn(hi[2 * j], hi[2 * j + 1]);
        }
    }
    const float   b2v   = __ldg(b2);
    const __half2 zero2 = __floats2half2_rn(0.f, 0.f);
    const __half2 one2  = __floats2half2_rn(1.f, 1.f);

    const __half* Ulo = g_U + l8 * 8;
    const __half* Uhi = g_U + 64 + l8 * 8;
    const __half* Vlo = g_V + l8 * 8;
    const __half* Vhi = g_V + 64 + l8 * 8;

    for (int e8 = gw * 8; e8 < E; e8 += nw * 8) {
        const int  eA = e8 + sub * 2;            // this slot's edges: eA, eA+1
        const int  eB = eA + 1;
        const bool vA = (eA < E);
        const bool vB = (eB < E);

        const int s0 = vA ? __ldg(ei + eA)     : 0;
        const int d0 = vA ? __ldg(ei + E + eA) : 0;
        const int s1 = vB ? __ldg(ei + eB)     : 0;
        const int d1 = vB ? __ldg(ei + E + eB) : 0;

        const size_t so0 = (size_t)s0 * HID;
        const size_t do0 = (size_t)d0 * HID;
        const size_t so1 = (size_t)s1 * HID;
        const size_t do1 = (size_t)d1 * HID;

        // All 8 gathers up front (MLP = 8 per lane)
        const uint4 u0l = *(const uint4*)(Ulo + so0);
        const uint4 u0h = *(const uint4*)(Uhi + so0);
        const uint4 v0l = *(const uint4*)(Vlo + do0);
        const uint4 v0h = *(const uint4*)(Vhi + do0);
        const uint4 u1l = *(const uint4*)(Ulo + so1);
        const uint4 u1h = *(const uint4*)(Uhi + so1);
        const uint4 v1l = *(const uint4*)(Vlo + do1);
        const uint4 v1h = *(const uint4*)(Vhi + do1);

        const __half2* u0lp = (const __half2*)&u0l;
        const __half2* u0hp = (const __half2*)&u0h;
        const __half2* v0lp = (const __half2*)&v0l;
        const __half2* v0hp = (const __half2*)&v0h;
        const __half2* u1lp = (const __half2*)&u1l;
        const __half2* u1hp = (const __half2*)&u1h;
        const __half2* v1lp = (const __half2*)&v1l;
        const __half2* v1hp = (const __half2*)&v1h;

        __half2 p0a = zero2, p0b = zero2, p1a = zero2, p1b = zero2;
        #pragma unroll
        for (int j = 0; j < 4; j++) {
            p0a = __hfma2(hfma2_relu(u0lp[j], one2, v0lp[j]), w2h[j],     p0a);
            p0b = __hfma2(hfma2_relu(u0hp[j], one2, v0hp[j]), w2h[4 + j], p0b);
            p1a = __hfma2(hfma2_relu(u1lp[j], one2, v1lp[j]), w2h[j],     p1a);
            p1b = __hfma2(hfma2_relu(u1hp[j], one2, v1hp[j]), w2h[4 + j], p1b);
        }

        const __half2 p0 = __hadd2(p0a, p0b);
        const __half2 p1 = __hadd2(p1a, p1b);
        float a0 = __low2float(p0) + __high2float(p0);
        float a1 = __low2float(p1) + __high2float(p1);

        // 3-level reduce within each 8-lane group (all 8 edges in parallel)
        #pragma unroll
        for (int o = 4; o; o >>= 1) {
            a0 += __shfl_xor_sync(0xffffffffu, a0, o);
            a1 += __shfl_xor_sync(0xffffffffu, a1, o);
        }

        if (l8 == 0) {
            if (vA) out[eA] = 1.0f / (1.0f + __expf(-(a0 + b2v)));
            if (vB) out[eB] = 1.0f / (1.0f + __expf(-(a1 + b2v)));
        }
    }
}

// ---------------------------------------------------------------------------
// inputs: z f32[100000*128], edge_index i32[2*1000000],
//         W1 f32[256*128], b1 f32[128], W2 f32[128], b2 f32[1]
// output: f32[1000000]
// ---------------------------------------------------------------------------
extern "C" void kernel_launch(void* const* d_in, const int* in_sizes, int n_in,
                              void* d_out, int out_size)
{
    (void)n_in; (void)out_size;
    const float* z  = (const float*)d_in[0];
    const int*   ei = (const int*)  d_in[1];
    const float* W1 = (const float*)d_in[2];
    const float* b1 = (const float*)d_in[3];
    const float* W2 = (const float*)d_in[4];
    const float* b2 = (const float*)d_in[5];

    const int n_nodes = in_sizes[0] / HID;
    const int E       = in_sizes[1] / 2;

    const int smem_bytes = (64 * LDA2 + KEXT * LDB2) * (int)sizeof(__half);  // 95,488 B
    cudaFuncSetAttribute(lp_precompute,
                         cudaFuncAttributeMaxDynamicSharedMemorySize, smem_bytes);

    lp_precompute<<<PGRID, 256, smem_bytes>>>(z, W1, b1, n_nodes);

    lp_edge<<<4440, 256>>>(ei, W2, b2, (float*)d_out, E);
}

// round 17
// speedup vs baseline: 1.3016x; 1.0504x over previous
#include <cuda_runtime.h>
#include <cuda_fp16.h>
#include <mma.h>
#include <cstdint>

using namespace nvcuda;

#define MAX_NODES 100000
#define HID   128
#define KEXT  144         // 128 Z dims + 1 bias row + 15 zero pad
#define LDA2  152         // sA row stride (halves): conflict-free ldmatrix
#define LDB2  264         // sB row stride (halves): 256 + 8 pad
#define NTILES 1563       // ceil(100000 / 64)
#define PGRID  296        // persistent CTAs = 148 SMs * 2

// Per-node projections, fp16 (51.2 MB total).
// g_U = Z @ W1[0:128,:] + b1 (bias folded via K-extension row); g_V = Z @ W1[128:256,:].
__device__ __half g_U[(size_t)MAX_NODES * HID];
__device__ __half g_V[(size_t)MAX_NODES * HID];

extern __shared__ char smem_raw[];

// ---------------------------------------------------------------------------
// Persistent fused precompute. R11 loop structure (frozen — R8/R13 overlap
// restructures regressed), but warp tiling changed 16x128 -> 32x64:
// per k-step 2 A-ldsm + 4 B-ldsm + 8 MMA (vs 1+8+8), i.e. 33% fewer LDSM
// at identical MMA and register cost.
// ---------------------------------------------------------------------------
__global__ void __launch_bounds__(256)
lp_precompute(const float* __restrict__ z,
              const float* __restrict__ W1,
              const float* __restrict__ b1,
              int n_nodes)
{
    __half* sA = (__half*)smem_raw;              // [64][LDA2]
    __half* sB = sA + 64 * LDA2;                 // [KEXT][LDB2]

    const int tid = threadIdx.x;

    // One-time B stage: combined [k][n]; n<128 -> W1[k][n], n>=128 -> W1[128+k][n-128]
    for (int idx = tid; idx < 128 * 64; idx += 256) {
        const int r  = idx >> 6;
        const int c4 = (idx & 63) << 2;
        const float* src = (c4 < 128)
            ? (W1 + (size_t)r * HID + c4)
            : (W1 + (size_t)(128 + r) * HID + (c4 - 128));
        const float4 f = *(const float4*)src;
        __half2 h[2];
        h[0] = __floats2half2_rn(f.x, f.y);
        h[1] = __floats2half2_rn(f.z, f.w);
        *(uint2*)(sB + r * LDB2 + c4) = *(uint2*)h;
    }
    // B rows 128..143: row 128 = [b1 | 0], remainder zero
    for (int idx = tid; idx < 16 * 64; idx += 256) {
        const int r  = 128 + (idx >> 6);
        const int c4 = (idx & 63) << 2;
        __half2 h[2];
        if (r == 128 && c4 < 128) {
            const float4 f = *(const float4*)(b1 + c4);
            h[0] = __floats2half2_rn(f.x, f.y);
            h[1] = __floats2half2_rn(f.z, f.w);
        } else {
            h[0] = h[1] = __floats2half2_rn(0.f, 0.f);
        }
        *(uint2*)(sB + r * LDB2 + c4) = *(uint2*)h;
    }
    // A constant cols 128..143: col 128 = 1.0 (bias multiplier), rest 0; set once
    for (int i = tid; i < 64 * 4; i += 256) {
        const int r  = i >> 2;
        const int c4 = 128 + (i & 3) * 4;
        __half h4[4];
        h4[0] = __float2half((c4 == 128) ? 1.0f : 0.0f);
        h4[1] = __float2half(0.0f);
        h4[2] = __float2half(0.0f);
        h4[3] = __float2half(0.0f);
        *(uint2*)(sA + r * LDA2 + c4) = *(uint2*)h4;
    }

    const int warpId = tid >> 5;
    const int wm = (warpId & 1) * 32;            // warp m offset (0/32)
    const int wn = (warpId >> 1) * 64;           // warp n offset (0/64/128/192)
    __half* const outb = (wn < 128) ? g_U : g_V;
    const int ocol = (wn < 128) ? wn : wn - 128;

    #pragma unroll 1
    for (int tile = blockIdx.x; tile < NTILES; tile += PGRID) {
        const int m0   = tile * 64;
        const int mrem = n_nodes - m0;

        __syncthreads();   // prior MMA done reading sA (and sB ready on t=0)

        // Stage A cols 0..127: Z fp32 -> fp16, zero-pad past-end rows
        for (int idx = tid; idx < 64 * 32; idx += 256) {
            const int r  = idx >> 5;
            const int c4 = (idx & 31) << 2;
            __half2 h[2];
            if (r < mrem) {
                const float4 f = *(const float4*)(z + (size_t)(m0 + r) * HID + c4);
                h[0] = __floats2half2_rn(f.x, f.y);
                h[1] = __floats2half2_rn(f.z, f.w);
            } else {
                h[0] = h[1] = __floats2half2_rn(0.f, 0.f);
            }
            *(uint2*)(sA + r * LDA2 + c4) = *(uint2*)h;
        }
        __syncthreads();

        if (m0 + wm < n_nodes) {                 // rows are zero-padded, MMA of pad rows harmless
            wmma::fragment<wmma::accumulator, 16, 16, 16, float> acc[2][4];
            #pragma unroll
            for (int i = 0; i < 2; i++)
                #pragma unroll
                for (int j = 0; j < 4; j++)
                    wmma::fill_fragment(acc[i][j], 0.0f);

            #pragma unroll
            for (int k0 = 0; k0 < KEXT; k0 += 16) {
                wmma::fragment<wmma::matrix_a, 16, 16, 16, __half, wmma::row_major> a[2];
                #pragma unroll
                for (int i = 0; i < 2; i++)
                    wmma::load_matrix_sync(a[i], sA + (wm + i * 16) * LDA2 + k0, LDA2);
                #pragma unroll
                for (int j = 0; j < 4; j++) {
                    wmma::fragment<wmma::matrix_b, 16, 16, 16, __half, wmma::row_major> b;
                    wmma::load_matrix_sync(b, sB + k0 * LDB2 + wn + j * 16, LDB2);
                    #pragma unroll
                    for (int i = 0; i < 2; i++)
                        wmma::mma_sync(acc[i][j], a[i], b, acc[i][j]);
                }
            }

            #pragma unroll
            for (int i = 0; i < 2; i++) {
                if (m0 + wm + i * 16 < n_nodes) {
                    #pragma unroll
                    for (int j = 0; j < 4; j++) {
                        wmma::fragment<wmma::accumulator, 16, 16, 16, __half> hacc;
                        #pragma unroll
                        for (int t = 0; t < hacc.num_elements; t++)
                            hacc.x[t] = __float2half(acc[i][j].x[t]);
                        wmma::store_matrix_sync(
                            outb + (size_t)(m0 + wm + i * 16) * HID + ocol + j * 16,
                            hacc, HID, wmma::mem_row_major);
                    }
                }
            }
        }
    }
}

// ---------------------------------------------------------------------------
// Edge kernel: 8 lanes per edge-slot, 4 slots per warp, 2 edges per slot per
// iteration (8 edges/warp/iter), with SOFTWARE-PIPELINED index loads: the
// next iteration's 4 indices load while the current gathers/math execute,
// removing the index->gather serial chain from the critical path.
// ---------------------------------------------------------------------------
__device__ __forceinline__ __half2 hfma2_relu(__half2 a, __half2 b, __half2 c) {
    uint32_t r;
    asm("fma.rn.relu.f16x2 %0, %1, %2, %3;"
        : "=r"(r)
        : "r"(*(const uint32_t*)&a), "r"(*(const uint32_t*)&b),
          "r"(*(const uint32_t*)&c));
    return *(__half2*)&r;
}

__global__ void __launch_bounds__(256)
lp_edge(const int* __restrict__ ei,
        const float* __restrict__ W2,
        const float* __restrict__ b2,
        float* __restrict__ out,
        int E)
{
    const int lane = threadIdx.x & 31;
    const int sub  = lane >> 3;                  // edge slot 0..3
    const int l8   = lane & 7;                   // dim group
    const int gw   = (blockIdx.x * blockDim.x + threadIdx.x) >> 5;
    const int nw   = (gridDim.x * blockDim.x) >> 5;

    __half2 w2h[8];
    {
        const float* lo = W2 + l8 * 8;
        const float* hi = W2 + 64 + l8 * 8;
        #pragma unroll
        for (int j = 0; j < 4; j++) {
            w2h[j]     = __floats2half2_rn(lo[2 * j], lo[2 * j + 1]);
            w2h[4 + j] = __floats2half2_rn(hi[2 * j], hi[2 * j + 1]);
        }
    }
    const float   b2v   = __ldg(b2);
    const __half2 zero2 = __floats2half2_rn(0.f, 0.f);
    const __half2 one2  = __floats2half2_rn(1.f, 1.f);

    const __half* Ulo = g_U + l8 * 8;
    const __half* Uhi = g_U + 64 + l8 * 8;
    const __half* Vlo = g_V + l8 * 8;
    const __half* Vhi = g_V + 64 + l8 * 8;

    const int step = nw * 8;
    int e8 = gw * 8;

    // Prologue: load first iteration's indices
    int s0 = 0, d0 = 0, s1 = 0, d1 = 0;
    if (e8 < E) {
        const int eA = e8 + sub * 2;
        const int eB = eA + 1;
        if (eA < E) { s0 = __ldg(ei + eA); d0 = __ldg(ei + E + eA); }
        if (eB < E) { s1 = __ldg(ei + eB); d1 = __ldg(ei + E + eB); }
    }

    for (; e8 < E; e8 += step) {
        const int  eA = e8 + sub * 2;
        const int  eB = eA + 1;
        const bool vA = (eA < E);
        const bool vB = (eB < E);

        const size_t so0 = (size_t)s0 * HID;
        const size_t do0 = (size_t)d0 * HID;
        const size_t so1 = (size_t)s1 * HID;
        const size_t do1 = (size_t)d1 * HID;

        // Issue all 8 gathers (MLP = 8 per lane)
        const uint4 u0l = *(const uint4*)(Ulo + so0);
        const uint4 u0h = *(const uint4*)(Uhi + so0);
        const uint4 v0l = *(const uint4*)(Vlo + do0);
        const uint4 v0h = *(const uint4*)(Vhi + do0);
        const uint4 u1l = *(const uint4*)(Ulo + so1);
        const uint4 u1h = *(const uint4*)(Uhi + so1);
        const uint4 v1l = *(const uint4*)(Vlo + do1);
        const uint4 v1h = *(const uint4*)(Vhi + do1);

        // Prefetch NEXT iteration's indices (overlaps with gather latency)
        int ns0 = 0, nd0 = 0, ns1 = 0, nd1 = 0;
        {
            const int ne8 = e8 + step;
            if (ne8 < E) {
                const int neA = ne8 + sub * 2;
                const int neB = neA + 1;
                if (neA < E) { ns0 = __ldg(ei + neA); nd0 = __ldg(ei + E + neA); }
                if (neB < E) { ns1 = __ldg(ei + neB); nd1 = __ldg(ei + E + neB); }
            }
        }

        const __half2* u0lp = (const __half2*)&u0l;
        const __half2* u0hp = (const __half2*)&u0h;
        const __half2* v0lp = (const __half2*)&v0l;
        const __half2* v0hp = (const __half2*)&v0h;
        const __half2* u1lp = (const __half2*)&u1l;
        const __half2* u1hp = (const __half2*)&u1h;
        const __half2* v1lp = (const __half2*)&v1l;
        const __half2* v1hp = (const __half2*)&v1h;

        __half2 p0a = zero2, p0b = zero2, p1a = zero2, p1b = zero2;
        #pragma unroll
        for (int j = 0; j < 4; j++) {
            p0a = __hfma2(hfma2_relu(u0lp[j], one2, v0lp[j]), w2h[j],     p0a);
            p0b = __hfma2(hfma2_relu(u0hp[j], one2, v0hp[j]), w2h[4 + j], p0b);
            p1a = __hfma2(hfma2_relu(u1lp[j], one2, v1lp[j]), w2h[j],     p1a);
            p1b = __hfma2(hfma2_relu(u1hp[j], one2, v1hp[j]), w2h[4 + j], p1b);
        }

        const __half2 p0 = __hadd2(p0a, p0b);
        const __half2 p1 = __hadd2(p1a, p1b);
        float a0 = __low2float(p0) + __high2float(p0);
        float a1 = __low2float(p1) + __high2float(p1);

        #pragma unroll
        for (int o = 4; o; o >>= 1) {
            a0 += __shfl_xor_sync(0xffffffffu, a0, o);
            a1 += __shfl_xor_sync(0xffffffffu, a1, o);
        }

        if (l8 == 0) {
            if (vA) out[eA] = 1.0f / (1.0f + __expf(-(a0 + b2v)));
            if (vB) out[eB] = 1.0f / (1.0f + __expf(-(a1 + b2v)));
        }

        s0 = ns0; d0 = nd0; s1 = ns1; d1 = nd1;
    }
}

// ---------------------------------------------------------------------------
// inputs: z f32[100000*128], edge_index i32[2*1000000],
//         W1 f32[256*128], b1 f32[128], W2 f32[128], b2 f32[1]
// output: f32[1000000]
// ---------------------------------------------------------------------------
extern "C" void kernel_launch(void* const* d_in, const int* in_sizes, int n_in,
                              void* d_out, int out_size)
{
    (void)n_in; (void)out_size;
    const float* z  = (const float*)d_in[0];
    const int*   ei = (const int*)  d_in[1];
    const float* W1 = (const float*)d_in[2];
    const float* b1 = (const float*)d_in[3];
    const float* W2 = (const float*)d_in[4];
    const float* b2 = (const float*)d_in[5];

    const int n_nodes = in_sizes[0] / HID;
    const int E       = in_sizes[1] / 2;

    const int smem_bytes = (64 * LDA2 + KEXT * LDB2) * (int)sizeof(__half);  // 95,488 B
    cudaFuncSetAttribute(lp_precompute,
                         cudaFuncAttributeMaxDynamicSharedMemorySize, smem_bytes);

    lp_precompute<<<PGRID, 256, smem_bytes>>>(z, W1, b1, n_nodes);

    lp_edge<<<4440, 256>>>(ei, W2, b2, (float*)d_out, E);
}